// round 16
// baseline (speedup 1.0000x reference)
#include <cuda_runtime.h>
#include <math.h>

#define BB 8
#define NN 4096
#define NPT 1024
#define NS 32
#define DPTS 61
#define CIN 64
#define M0 128
#define M1 256
#define M2 512
#define LL (NPT*NS)          /* 32768 */
#define BN_EPS 1e-5f
#define STD_MIN 1e-6f
#define SPLITMAX 32
#define TRBLOCKS 977         /* transpose tail blocks appended to knn grid */

// ---------------- scratch (static device allocations) ----------------
__device__ float g_x[(size_t)BB*CIN*LL];       // standardized grouped input [b][c][l]
__device__ float g_inter[(size_t)BB*M0*LL];    // [b][128][l]
__device__ float g_feat[(size_t)BB*M1*LL];     // [b][256][l]
__device__ float g_logits[(size_t)BB*LL];
__device__ float g_agg[(size_t)BB*M1*NPT];     // [b][256][p]
__device__ float g_ptsT[(size_t)BB*NN*DPTS];   // points transposed [b][n][c]
__device__ int   g_idx[BB*NPT*NS];
__device__ float g_p1[512*SPLITMAX], g_p2[512*SPLITMAX];
__device__ float g_W1f[M0*CIN]; __device__ float g_b1f[M0];
__device__ float g_W2f[M1*M0];  __device__ float g_b2f[M1];
__device__ float g_Wgf[M2*M1];  __device__ float g_bgf[M2];

__device__ __forceinline__ unsigned long long umin64(unsigned long long a, unsigned long long b){
    return a < b ? a : b;
}

// ---------------- KNN (proven) + fused points transpose tail ----------------
__global__ __launch_bounds__(256)
void knn_kernel(const float* __restrict__ xyz, const int* __restrict__ cent,
                const float* __restrict__ points, float* __restrict__ out_newxyz)
{
    __shared__ unsigned long long cand[NN];   // 32 KB
    __shared__ unsigned long long warpmin[8];
    __shared__ unsigned long long gminS;
    const int tid = threadIdx.x;
    if (blockIdx.x >= BB*NPT) {
        // transpose tail: points [B,61,N] -> g_ptsT [B,N,61]
        const int base = (blockIdx.x - BB*NPT)*256 + tid;
        for (int i = base; i < BB*DPTS*NN; i += TRBLOCKS*256) {
            int n = i % NN; int t = i / NN;
            int c = t % DPTS; int b = t / DPTS;
            g_ptsT[((size_t)(b*NN + n))*DPTS + c] = points[i];
        }
        return;
    }
    const int b = blockIdx.x / NPT, p = blockIdx.x % NPT;
    const int ci = cent[b*NPT + p];
    const float cx = xyz[(b*NN + ci)*3 + 0];
    const float cy = xyz[(b*NN + ci)*3 + 1];
    const float cz = xyz[(b*NN + ci)*3 + 2];
    unsigned long long lm = ~0ull;
    for (int j = tid; j < NN; j += 256) {
        float dx = xyz[(b*NN + j)*3+0] - cx;
        float dy = xyz[(b*NN + j)*3+1] - cy;
        float dz = xyz[(b*NN + j)*3+2] - cz;
        float d = dx*dx + dy*dy + dz*dz;   // >= 0: float bits order-preserving
        unsigned long long key = ((unsigned long long)__float_as_uint(d) << 32) | (unsigned)j;
        cand[j] = key;
        lm = umin64(lm, key);
    }
    if (out_newxyz && tid < 3)
        out_newxyz[(b*NPT + p)*3 + tid] = (tid==0 ? cx : (tid==1 ? cy : cz));
    __syncthreads();
    const int lane = tid & 31, wid = tid >> 5;
    for (int r = 0; r < NS; r++) {
        unsigned long long v = lm;
        #pragma unroll
        for (int o = 16; o > 0; o >>= 1)
            v = umin64(v, __shfl_xor_sync(0xffffffffu, v, o));
        if (lane == 0) warpmin[wid] = v;
        __syncthreads();
        if (wid == 0) {
            unsigned long long m = (lane < 8) ? warpmin[lane] : ~0ull;
            #pragma unroll
            for (int o = 4; o > 0; o >>= 1)
                m = umin64(m, __shfl_xor_sync(0xffffffffu, m, o));
            if (lane == 0) {
                gminS = m;
                g_idx[blockIdx.x*NS + r] = (int)(m & 0xffffffffull);
            }
        }
        __syncthreads();
        const int bi = (int)(gminS & 0xffffffffull);
        if ((bi & 255) == tid) {          // owner-only; cand slice is thread-private
            cand[bi] = ~0ull;
            unsigned long long nm = ~0ull;
            #pragma unroll
            for (int j = tid; j < NN; j += 256) nm = umin64(nm, cand[j]);
            lm = nm;
        }
    }
}

// ------------- gather + per-group standardize -> g_x -------------
__global__ __launch_bounds__(256)
void group_std_kernel(const float* __restrict__ xyz, const int* __restrict__ cent)
{
    __shared__ int idxS[NS];
    __shared__ float cS[3];
    __shared__ float v[CIN*33];     // padded [c][33] to avoid bank conflicts
    __shared__ float redS[256];
    const int b = blockIdx.x / NPT, p = blockIdx.x % NPT;
    const int tid = threadIdx.x;
    if (tid < NS) idxS[tid] = g_idx[blockIdx.x*NS + tid];
    if (tid < 3) {
        int ci = cent[b*NPT + p];
        cS[tid] = xyz[(b*NN + ci)*3 + tid];
    }
    __syncthreads();
    float ls = 0.f;
    #pragma unroll
    for (int u = tid; u < CIN*NS; u += 256) {
        int s = u >> 6, c = u & 63;     // c fastest
        int gi = idxS[s];
        float val = (c < 3) ? (xyz[(b*NN + gi)*3 + c] - cS[c])
                            : g_ptsT[((size_t)(b*NN + gi))*DPTS + (c-3)];
        v[c*33 + s] = val; ls += val;
    }
    redS[tid] = ls; __syncthreads();
    for (int s = 128; s > 0; s >>= 1) { if (tid < s) redS[tid] += redS[tid+s]; __syncthreads(); }
    const float mean = redS[0] * (1.f/(CIN*NS));
    __syncthreads();
    float lq = 0.f;
    #pragma unroll
    for (int u = tid; u < CIN*NS; u += 256) {
        int c = u >> 5, s = u & 31;
        float d = v[c*33 + s]-mean; lq += d*d;
    }
    redS[tid] = lq; __syncthreads();
    for (int s = 128; s > 0; s >>= 1) { if (tid < s) redS[tid] += redS[tid+s]; __syncthreads(); }
    const float var = redS[0] * (1.f/(CIN*NS));
    const float inv = 1.f / fmaxf(sqrtf(var), STD_MIN);
    #pragma unroll
    for (int u = tid; u < CIN*NS; u += 256) {
        int c = u >> 5, s = u & 31;
        g_x[((size_t)(b*CIN + c))*LL + p*NS + s] = (v[c*33 + s]-mean)*inv;
    }
}

// --------- stage A: per-(channel, slice) partial sums, float4 + fp32 accum ---------
__global__ void chan_stats_part_kernel(const float* __restrict__ T, int C, int Lb, int split)
{
    __shared__ float r1[256], r2[256];
    const int c = blockIdx.x, sl = blockIdx.y, tid = threadIdx.x;
    const int chunk = Lb / split;
    float s1 = 0.f, s2 = 0.f;
    for (int b = 0; b < BB; b++) {
        const float* base = T + ((size_t)(b*C + c))*Lb + sl*chunk;
        for (int l = tid*4; l < chunk; l += 1024) {
            float4 v = *(const float4*)(base + l);
            s1 += (v.x + v.y) + (v.z + v.w);
            s2 += (v.x*v.x + v.y*v.y) + (v.z*v.z + v.w*v.w);
        }
    }
    r1[tid]=s1; r2[tid]=s2; __syncthreads();
    for (int s=128;s>0;s>>=1){ if(tid<s){r1[tid]+=r1[tid+s]; r2[tid]+=r2[tid+s];} __syncthreads(); }
    if (tid==0) { g_p1[c*SPLITMAX + sl] = r1[0]; g_p2[c*SPLITMAX + sl] = r2[0]; }
}

// --------- fused stage B: fold W (y==0) + fold bias (y==1); stats recomputed locally ---------
__global__ void bn_fold_kernel(const float* __restrict__ W, const float* __restrict__ gamma,
                               const float* __restrict__ beta,
                               const float* __restrict__ bias, const float* __restrict__ bias2,
                               int M, int K, int Lb, int split,
                               float* __restrict__ Wf, float* __restrict__ bf)
{
    const int tid = threadIdx.x;
    __shared__ float sS[512], tS[512];
    for (int c = tid; c < K; c += 256) {
        double s1 = 0.0, s2 = 0.0;
        for (int i = 0; i < split; i++) {
            s1 += (double)g_p1[c*SPLITMAX + i];
            s2 += (double)g_p2[c*SPLITMAX + i];
        }
        double n = (double)BB*Lb;
        double m = s1/n;
        float var = (float)(s2/n - m*m);
        float sc = gamma[c] * rsqrtf(var + BN_EPS);
        sS[c] = sc;
        tS[c] = beta[c] - (float)m*sc;
    }
    __syncthreads();
    if (blockIdx.y == 0) {
        for (int i = blockIdx.x*256 + tid; i < M*K; i += gridDim.x*256) {
            int k = i % K;
            Wf[i] = W[i]*sS[k];
        }
    } else {
        for (int o = blockIdx.x*256 + tid; o < M; o += gridDim.x*256) {
            float acc = bias[o] + (bias2 ? bias2[o] : 0.f);
            for (int i = 0; i < K; i++) acc += W[o*K+i]*tS[i];
            bf[o] = acc;
        }
    }
}

// --------- packed-f32x2 GEMM (R14 proven, KT=16): C = relu(A1@X1 (+ A2@X2) + bias) ---------
template<int MT, bool RELU>
__global__ __launch_bounds__(256, 2)
void gemm_kernel(const float* __restrict__ A1, const float* __restrict__ X1, int K1,
                 const float* __restrict__ A2, const float* __restrict__ X2, int K2,
                 const float* __restrict__ bias, float* __restrict__ C,
                 int M, int Lb)
{
    constexpr int RM = MT/16;
    __shared__ float2 As[16][MT];   // duplicated pairs (a,a)
    __shared__ float  Xs[16][128];
    const int tid = threadIdx.x;
    const int tx = tid & 15, ty = tid >> 4;
    const int colg = blockIdx.x * 128;
    const int b = colg / Lb;
    const int n0 = colg % Lb;
    const int m0 = blockIdx.y * MT;
    unsigned long long acc[RM][4];
    #pragma unroll
    for (int r=0;r<RM;r++)
        #pragma unroll
        for (int c=0;c<4;c++) acc[r][c]=0ull;

    #pragma unroll 1
    for (int src = 0; src < 2; src++) {
        const float* A = src ? A2 : A1;
        const float* X = src ? X2 : X1;
        const int K = src ? K2 : K1;
        if (K == 0) continue;
        for (int kt = 0; kt < K; kt += 16) {
            #pragma unroll
            for (int i = 0; i < MT/16; i++) {
                int li = tid + i*256;
                int m = li >> 4, k = li & 15;
                float av = A[(m0+m)*K + kt + k];
                As[k][m] = make_float2(av, av);
            }
            #pragma unroll
            for (int i = 0; i < 8; i++) {
                int li = tid + i*256;
                int k = li >> 7, n = li & 127;
                Xs[k][n] = X[((size_t)(b*K + kt + k))*Lb + n0 + n];
            }
            __syncthreads();
            #pragma unroll
            for (int k = 0; k < 16; k++) {
                unsigned long long a[RM], x[4];
                const unsigned long long* ap = (const unsigned long long*)&As[k][ty*RM];
                #pragma unroll
                for (int r=0;r<RM;r++) a[r] = ap[r];
                const unsigned long long* xp = (const unsigned long long*)&Xs[k][tx*8];
                #pragma unroll
                for (int c=0;c<4;c++) x[c] = xp[c];
                #pragma unroll
                for (int r=0;r<RM;r++)
                    #pragma unroll
                    for (int c=0;c<4;c++)
                        asm("fma.rn.f32x2 %0, %1, %2, %0;"
                            : "+l"(acc[r][c]) : "l"(a[r]), "l"(x[c]));
            }
            __syncthreads();
        }
    }
    #pragma unroll
    for (int r=0;r<RM;r++) {
        int m = m0 + ty*RM + r;
        float bv = bias[m];
        float vals[8];
        #pragma unroll
        for (int c=0;c<4;c++) {
            unsigned long long A = acc[r][c];
            float lo = __uint_as_float((unsigned)A);
            float hi = __uint_as_float((unsigned)(A>>32));
            lo += bv; hi += bv;
            if (RELU) { lo = fmaxf(lo,0.f); hi = fmaxf(hi,0.f); }
            vals[2*c] = lo; vals[2*c+1] = hi;
        }
        float4* Cp = (float4*)(C + ((size_t)(b*M + m))*Lb + n0 + tx*8);
        Cp[0] = make_float4(vals[0],vals[1],vals[2],vals[3]);
        Cp[1] = make_float4(vals[4],vals[5],vals[6],vals[7]);
    }
}

// --------- attention GEMM (R14 proven, KT=16) with fused logits epilogue ---------
__global__ __launch_bounds__(256, 2)
void attn_gemm_kernel(const float* __restrict__ Wa1, const float* __restrict__ X,
                      const float* __restrict__ ba1, const float* __restrict__ Wa2,
                      const float* __restrict__ ba2)
{
    constexpr int MT = 64, RM = 4, K = M1;
    __shared__ float2 As[16][MT];
    __shared__ float  Xs[16][128];
    __shared__ float  red[16][128];
    const int tid = threadIdx.x;
    const int tx = tid & 15, ty = tid >> 4;
    const int colg = blockIdx.x * 128;
    const int b = colg / LL;
    const int n0 = colg % LL;
    unsigned long long acc[RM][4];
    #pragma unroll
    for (int r=0;r<RM;r++)
        #pragma unroll
        for (int c=0;c<4;c++) acc[r][c]=0ull;

    for (int kt = 0; kt < K; kt += 16) {
        #pragma unroll
        for (int i = 0; i < MT/16; i++) {
            int li = tid + i*256;
            int m = li >> 4, k = li & 15;
            float av = Wa1[m*K + kt + k];
            As[k][m] = make_float2(av, av);
        }
        #pragma unroll
        for (int i = 0; i < 8; i++) {
            int li = tid + i*256;
            int k = li >> 7, n = li & 127;
            Xs[k][n] = X[((size_t)(b*K + kt + k))*LL + n0 + n];
        }
        __syncthreads();
        #pragma unroll
        for (int k = 0; k < 16; k++) {
            unsigned long long a[RM], x[4];
            const unsigned long long* ap = (const unsigned long long*)&As[k][ty*RM];
            #pragma unroll
            for (int r=0;r<RM;r++) a[r] = ap[r];
            const unsigned long long* xp = (const unsigned long long*)&Xs[k][tx*8];
            #pragma unroll
            for (int c=0;c<4;c++) x[c] = xp[c];
            #pragma unroll
            for (int r=0;r<RM;r++)
                #pragma unroll
                for (int c=0;c<4;c++)
                    asm("fma.rn.f32x2 %0, %1, %2, %0;"
                        : "+l"(acc[r][c]) : "l"(a[r]), "l"(x[c]));
        }
        __syncthreads();
    }
    float part[8];
    #pragma unroll
    for (int k=0;k<8;k++) part[k]=0.f;
    #pragma unroll
    for (int r=0;r<RM;r++) {
        int m = ty*RM + r;
        float bv = ba1[m], w2 = Wa2[m];
        #pragma unroll
        for (int c=0;c<4;c++) {
            unsigned long long A = acc[r][c];
            float lo = fmaxf(__uint_as_float((unsigned)A) + bv, 0.f);
            float hi = fmaxf(__uint_as_float((unsigned)(A>>32)) + bv, 0.f);
            part[2*c]   += w2*lo;
            part[2*c+1] += w2*hi;
        }
    }
    #pragma unroll
    for (int k=0;k<8;k++) red[ty][tx*8+k] = part[k];
    __syncthreads();
    #pragma unroll
    for (int s=8;s>0;s>>=1) {
        if (ty < s) {
            #pragma unroll
            for (int k=0;k<8;k++) red[ty][tx*8+k] += red[ty+s][tx*8+k];
        }
        __syncthreads();
    }
    if (ty == 0) {
        float bb = ba2[0];
        #pragma unroll
        for (int k=0;k<8;k++)
            g_logits[(size_t)b*LL + n0 + tx*8 + k] = red[0][tx*8+k] + bb;
    }
}

// --------- softmax over the 32 neighbors + weighted aggregation ---------
__global__ __launch_bounds__(256)
void softagg_kernel()
{
    __shared__ float wS[NS];
    const int b = blockIdx.x / NPT, p = blockIdx.x % NPT;
    const int tid = threadIdx.x;
    if (tid < 32) {
        float lg = g_logits[b*LL + p*NS + tid];
        float m = lg;
        #pragma unroll
        for (int o=16;o>0;o>>=1) m = fmaxf(m, __shfl_xor_sync(0xffffffffu, m, o));
        float e = expf(lg - m);
        float s = e;
        #pragma unroll
        for (int o=16;o>0;o>>=1) s += __shfl_xor_sync(0xffffffffu, s, o);
        wS[tid] = e / s;
    }
    __syncthreads();
    const float4* f = (const float4*)(g_feat + ((size_t)(b*M1 + tid))*LL + p*NS);
    float a = 0.f;
    #pragma unroll
    for (int i = 0; i < 8; i++) {
        float4 v = f[i];
        a += v.x*wS[4*i] + v.y*wS[4*i+1] + v.z*wS[4*i+2] + v.w*wS[4*i+3];
    }
    g_agg[((size_t)(b*M1 + tid))*NPT + p] = a;
}

// ---------------------------------------------------------------
extern "C" void kernel_launch(void* const* d_in, const int* in_sizes, int n_in,
                              void* d_out, int out_size)
{
    const float* xyz    = (const float*)d_in[0];
    const float* points = (const float*)d_in[1];
    const int*   cent   = (const int*)  d_in[2];
    const float* gamma0 = (const float*)d_in[3];  const float* beta0 = (const float*)d_in[4];
    const float* W1     = (const float*)d_in[5];  const float* b1    = (const float*)d_in[6];
    const float* gamma1 = (const float*)d_in[7];  const float* beta1 = (const float*)d_in[8];
    const float* W2     = (const float*)d_in[9];  const float* b2    = (const float*)d_in[10];
    const float* Wres   = (const float*)d_in[11]; const float* bres  = (const float*)d_in[12];
    const float* Wa1    = (const float*)d_in[13]; const float* ba1   = (const float*)d_in[14];
    const float* Wa2    = (const float*)d_in[15]; const float* ba2   = (const float*)d_in[16];
    const float* gamma2 = (const float*)d_in[17]; const float* beta2 = (const float*)d_in[18];
    const float* Wg     = (const float*)d_in[19]; const float* bg    = (const float*)d_in[20];

    float* out = (float*)d_out;
    const int gf_elems = BB*M2*NPT;                 // 4,194,304
    float* out_gf = out + (out_size - gf_elems);    // gf goes last
    float* out_nx = (out_size > gf_elems) ? out : nullptr;

    float *px, *pinter, *pfeat, *pagg;
    float *pW1f, *pb1f, *pW2f, *pb2f, *pWgf, *pbgf;
    cudaGetSymbolAddress((void**)&px,     g_x);
    cudaGetSymbolAddress((void**)&pinter, g_inter);
    cudaGetSymbolAddress((void**)&pfeat,  g_feat);
    cudaGetSymbolAddress((void**)&pagg,   g_agg);
    cudaGetSymbolAddress((void**)&pW1f,   g_W1f);
    cudaGetSymbolAddress((void**)&pb1f,   g_b1f);
    cudaGetSymbolAddress((void**)&pW2f,   g_W2f);
    cudaGetSymbolAddress((void**)&pb2f,   g_b2f);
    cudaGetSymbolAddress((void**)&pWgf,   g_Wgf);
    cudaGetSymbolAddress((void**)&pbgf,   g_bgf);

    // 1. KNN + centroid coord output + fused points transpose (tail blocks)
    knn_kernel<<<BB*NPT + TRBLOCKS, 256>>>(xyz, cent, points, out_nx);
    // 2. gather + standardize
    group_std_kernel<<<BB*NPT, 256>>>(xyz, cent);
    // 3. BN0 stats + fold into W1 (fused)
    chan_stats_part_kernel<<<dim3(CIN, 32), 256>>>(px, CIN, LL, 32);
    bn_fold_kernel<<<dim3(32, 2), 256>>>(W1, gamma0, beta0, b1, nullptr,
                                         M0, CIN, LL, 32, pW1f, pb1f);
    // 4. inter = relu(W1' x + b1')          [f32x2 KT=16]
    gemm_kernel<128,true><<<dim3(BB*LL/128, 1), 256>>>(pW1f, px, CIN, nullptr, nullptr, 0,
                                                       pb1f, pinter, M0, LL);
    // 5. BN1 stats + fold into W2 (bias includes bres)
    chan_stats_part_kernel<<<dim3(M0, 16), 256>>>(pinter, M0, LL, 16);
    bn_fold_kernel<<<dim3(128, 2), 256>>>(W2, gamma1, beta1, b2, bres,
                                          M1, M0, LL, 16, pW2f, pb2f);
    // 6. feat = relu(W2' inter + Wres x + b')   [f32x2 dual-K KT=16]
    gemm_kernel<128,true><<<dim3(BB*LL/128, 2), 256>>>(pW2f, pinter, M0, Wres, px, CIN,
                                                       pb2f, pfeat, M1, LL);
    // 7. attention: h in-register, logits fused into GEMM epilogue
    attn_gemm_kernel<<<BB*LL/128, 256>>>(Wa1, pfeat, ba1, Wa2, ba2);
    softagg_kernel<<<BB*NPT, 256>>>();
    // 8. BN2 stats + fold into Wg
    chan_stats_part_kernel<<<dim3(M1, 4), 256>>>(pagg, M1, NPT, 4);
    bn_fold_kernel<<<dim3(512, 2), 256>>>(Wg, gamma2, beta2, bg, nullptr,
                                          M2, M1, NPT, 4, pWgf, pbgf);
    // 9. gf = relu(Wg' agg + bg')           [f32x2 KT=16]
    gemm_kernel<128,true><<<dim3(BB*NPT/128, 4), 256>>>(pWgf, pagg, M1, nullptr, nullptr, 0,
                                                        pbgf, out_gf, M2, NPT);
}

// round 17
// speedup vs baseline: 1.0474x; 1.0474x over previous
#include <cuda_runtime.h>
#include <math.h>

#define BB 8
#define NN 4096
#define NPT 1024
#define NS 32
#define DPTS 61
#define CIN 64
#define M0 128
#define M1 256
#define M2 512
#define LL (NPT*NS)          /* 32768 */
#define BN_EPS 1e-5f
#define STD_MIN 1e-6f
#define SPLITMAX 32

// ---------------- scratch (static device allocations) ----------------
__device__ float g_x[(size_t)BB*CIN*LL];       // standardized grouped input [b][c][l]
__device__ float g_inter[(size_t)BB*M0*LL];    // [b][128][l]
__device__ float g_feat[(size_t)BB*M1*LL];     // [b][256][l]
__device__ float g_logits[(size_t)BB*LL];
__device__ float g_agg[(size_t)BB*M1*NPT];     // [b][256][p]
__device__ float g_ptsT[(size_t)BB*NN*DPTS];   // points transposed [b][n][c]
__device__ int   g_idx[BB*NPT*NS];
__device__ float g_p1[512*SPLITMAX], g_p2[512*SPLITMAX];
__device__ float g_mean[512], g_var[512];
__device__ float g_W1f[M0*CIN]; __device__ float g_b1f[M0];
__device__ float g_W2f[M1*M0];  __device__ float g_b2f[M1];
__device__ float g_Wgf[M2*M1];  __device__ float g_bgf[M2];

__device__ __forceinline__ unsigned long long umin64(unsigned long long a, unsigned long long b){
    return a < b ? a : b;
}

// ---------------- KNN v1 (proven): 32 smallest dists per centroid ----------------
__global__ __launch_bounds__(256)
void knn_kernel(const float* __restrict__ xyz, const int* __restrict__ cent,
                float* __restrict__ out_newxyz)
{
    __shared__ unsigned long long cand[NN];   // 32 KB
    __shared__ unsigned long long warpmin[8];
    __shared__ unsigned long long gminS;
    const int b = blockIdx.x / NPT, p = blockIdx.x % NPT;
    const int tid = threadIdx.x;
    const int ci = cent[b*NPT + p];
    const float cx = xyz[(b*NN + ci)*3 + 0];
    const float cy = xyz[(b*NN + ci)*3 + 1];
    const float cz = xyz[(b*NN + ci)*3 + 2];
    unsigned long long lm = ~0ull;
    for (int j = tid; j < NN; j += 256) {
        float dx = xyz[(b*NN + j)*3+0] - cx;
        float dy = xyz[(b*NN + j)*3+1] - cy;
        float dz = xyz[(b*NN + j)*3+2] - cz;
        float d = dx*dx + dy*dy + dz*dz;   // >= 0: float bits order-preserving
        unsigned long long key = ((unsigned long long)__float_as_uint(d) << 32) | (unsigned)j;
        cand[j] = key;
        lm = umin64(lm, key);
    }
    if (out_newxyz && tid < 3)
        out_newxyz[(b*NPT + p)*3 + tid] = (tid==0 ? cx : (tid==1 ? cy : cz));
    __syncthreads();
    const int lane = tid & 31, wid = tid >> 5;
    for (int r = 0; r < NS; r++) {
        unsigned long long v = lm;
        #pragma unroll
        for (int o = 16; o > 0; o >>= 1)
            v = umin64(v, __shfl_xor_sync(0xffffffffu, v, o));
        if (lane == 0) warpmin[wid] = v;
        __syncthreads();
        if (wid == 0) {
            unsigned long long m = (lane < 8) ? warpmin[lane] : ~0ull;
            #pragma unroll
            for (int o = 4; o > 0; o >>= 1)
                m = umin64(m, __shfl_xor_sync(0xffffffffu, m, o));
            if (lane == 0) {
                gminS = m;
                g_idx[blockIdx.x*NS + r] = (int)(m & 0xffffffffull);
            }
        }
        __syncthreads();
        const int bi = (int)(gminS & 0xffffffffull);
        if ((bi & 255) == tid) {          // owner-only; cand slice is thread-private
            cand[bi] = ~0ull;
            unsigned long long nm = ~0ull;
            #pragma unroll
            for (int j = tid; j < NN; j += 256) nm = umin64(nm, cand[j]);
            lm = nm;
        }
    }
}

// ---------------- transpose points [B,61,N] -> [B,N,61] ----------------
__global__ void pts_transpose_kernel(const float* __restrict__ points)
{
    int i = blockIdx.x*256 + threadIdx.x;           // over B*DPTS*NN, n fastest
    if (i >= BB*DPTS*NN) return;
    int n = i % NN; int t = i / NN;
    int c = t % DPTS; int b = t / DPTS;
    g_ptsT[((size_t)(b*NN + n))*DPTS + c] = points[i];
}

// ------------- gather + per-group standardize -> g_x -------------
__global__ __launch_bounds__(256)
void group_std_kernel(const float* __restrict__ xyz, const int* __restrict__ cent)
{
    __shared__ int idxS[NS];
    __shared__ float cS[3];
    __shared__ float v[CIN*33];     // padded [c][33] to avoid bank conflicts
    __shared__ float redS[256];
    const int b = blockIdx.x / NPT, p = blockIdx.x % NPT;
    const int tid = threadIdx.x;
    if (tid < NS) idxS[tid] = g_idx[blockIdx.x*NS + tid];
    if (tid < 3) {
        int ci = cent[b*NPT + p];
        cS[tid] = xyz[(b*NN + ci)*3 + tid];
    }
    __syncthreads();
    float ls = 0.f;
    #pragma unroll
    for (int u = tid; u < CIN*NS; u += 256) {
        int s = u >> 6, c = u & 63;     // c fastest
        int gi = idxS[s];
        float val = (c < 3) ? (xyz[(b*NN + gi)*3 + c] - cS[c])
                            : g_ptsT[((size_t)(b*NN + gi))*DPTS + (c-3)];
        v[c*33 + s] = val; ls += val;
    }
    redS[tid] = ls; __syncthreads();
    for (int s = 128; s > 0; s >>= 1) { if (tid < s) redS[tid] += redS[tid+s]; __syncthreads(); }
    const float mean = redS[0] * (1.f/(CIN*NS));
    __syncthreads();
    float lq = 0.f;
    #pragma unroll
    for (int u = tid; u < CIN*NS; u += 256) {
        int c = u >> 5, s = u & 31;
        float d = v[c*33 + s]-mean; lq += d*d;
    }
    redS[tid] = lq; __syncthreads();
    for (int s = 128; s > 0; s >>= 1) { if (tid < s) redS[tid] += redS[tid+s]; __syncthreads(); }
    const float var = redS[0] * (1.f/(CIN*NS));
    const float inv = 1.f / fmaxf(sqrtf(var), STD_MIN);
    #pragma unroll
    for (int u = tid; u < CIN*NS; u += 256) {
        int c = u >> 5, s = u & 31;
        g_x[((size_t)(b*CIN + c))*LL + p*NS + s] = (v[c*33 + s]-mean)*inv;
    }
}

// --------- stage A: per-(channel, slice) partial sums, float4 + fp32 accum ---------
__global__ void chan_stats_part_kernel(const float* __restrict__ T, int C, int Lb, int split)
{
    __shared__ float r1[256], r2[256];
    const int c = blockIdx.x, sl = blockIdx.y, tid = threadIdx.x;
    const int chunk = Lb / split;
    float s1 = 0.f, s2 = 0.f;
    for (int b = 0; b < BB; b++) {
        const float* base = T + ((size_t)(b*C + c))*Lb + sl*chunk;
        for (int l = tid*4; l < chunk; l += 1024) {
            float4 v = *(const float4*)(base + l);
            s1 += (v.x + v.y) + (v.z + v.w);
            s2 += (v.x*v.x + v.y*v.y) + (v.z*v.z + v.w*v.w);
        }
    }
    r1[tid]=s1; r2[tid]=s2; __syncthreads();
    for (int s=128;s>0;s>>=1){ if(tid<s){r1[tid]+=r1[tid+s]; r2[tid]+=r2[tid+s];} __syncthreads(); }
    if (tid==0) { g_p1[c*SPLITMAX + sl] = r1[0]; g_p2[c*SPLITMAX + sl] = r2[0]; }
}

// --------- fused stage B: finalize stats + fold W + fold bias, one launch ---------
__global__ void bn_fold_kernel(const float* __restrict__ W, const float* __restrict__ gamma,
                               const float* __restrict__ beta,
                               const float* __restrict__ bias, const float* __restrict__ bias2,
                               int M, int K, int Lb, int split,
                               float* __restrict__ Wf, float* __restrict__ bf)
{
    const int tid = threadIdx.x;
    if (blockIdx.y == 0) {
        if (blockIdx.x == 0) {
            for (int c = tid; c < K; c += 256) {
                double s1 = 0.0, s2 = 0.0;
                for (int i = 0; i < split; i++) {
                    s1 += (double)g_p1[c*SPLITMAX + i];
                    s2 += (double)g_p2[c*SPLITMAX + i];
                }
                double n = (double)BB*Lb;
                double m = s1/n;
                g_mean[c] = (float)m;
                g_var[c]  = (float)(s2/n - m*m);
            }
        }
        return;
    }
    __shared__ float sS[512], tS[512];
    for (int c = tid; c < K; c += 256) {
        double s1 = 0.0, s2 = 0.0;
        for (int i = 0; i < split; i++) {
            s1 += (double)g_p1[c*SPLITMAX + i];
            s2 += (double)g_p2[c*SPLITMAX + i];
        }
        double n = (double)BB*Lb;
        double m = s1/n;
        float var = (float)(s2/n - m*m);
        float sc = gamma[c] * rsqrtf(var + BN_EPS);
        sS[c] = sc;
        tS[c] = beta[c] - (float)m*sc;
    }
    __syncthreads();
    if (blockIdx.y == 1) {
        for (int i = blockIdx.x*256 + tid; i < M*K; i += gridDim.x*256) {
            int k = i % K;
            Wf[i] = W[i]*sS[k];
        }
    } else {
        for (int o = blockIdx.x*256 + tid; o < M; o += gridDim.x*256) {
            float acc = bias[o] + (bias2 ? bias2[o] : 0.f);
            for (int i = 0; i < K; i++) acc += W[o*K+i]*tS[i];
            bf[o] = acc;
        }
    }
}

// --------- packed-f32x2 GEMM (proven): C = relu(A1@X1 (+ A2@X2) + bias) ---------
template<int MT, bool RELU>
__global__ __launch_bounds__(256, 2)
void gemm_kernel(const float* __restrict__ A1, const float* __restrict__ X1, int K1,
                 const float* __restrict__ A2, const float* __restrict__ X2, int K2,
                 const float* __restrict__ bias, float* __restrict__ C,
                 int M, int Lb)
{
    constexpr int RM = MT/16;
    __shared__ float2 As[16][MT];   // duplicated pairs (a,a)
    __shared__ float  Xs[16][128];
    const int tid = threadIdx.x;
    const int tx = tid & 15, ty = tid >> 4;
    const int colg = blockIdx.x * 128;
    const int b = colg / Lb;
    const int n0 = colg % Lb;
    const int m0 = blockIdx.y * MT;
    unsigned long long acc[RM][4];
    #pragma unroll
    for (int r=0;r<RM;r++)
        #pragma unroll
        for (int c=0;c<4;c++) acc[r][c]=0ull;

    #pragma unroll 1
    for (int src = 0; src < 2; src++) {
        const float* A = src ? A2 : A1;
        const float* X = src ? X2 : X1;
        const int K = src ? K2 : K1;
        if (K == 0) continue;
        for (int kt = 0; kt < K; kt += 16) {
            #pragma unroll
            for (int i = 0; i < MT/16; i++) {
                int li = tid + i*256;
                int m = li >> 4, k = li & 15;
                float av = A[(m0+m)*K + kt + k];
                As[k][m] = make_float2(av, av);
            }
            #pragma unroll
            for (int i = 0; i < 8; i++) {
                int li = tid + i*256;
                int k = li >> 7, n = li & 127;
                Xs[k][n] = X[((size_t)(b*K + kt + k))*Lb + n0 + n];
            }
            __syncthreads();
            #pragma unroll
            for (int k = 0; k < 16; k++) {
                unsigned long long a[RM], x[4];
                const unsigned long long* ap = (const unsigned long long*)&As[k][ty*RM];
                #pragma unroll
                for (int r=0;r<RM;r++) a[r] = ap[r];
                const unsigned long long* xp = (const unsigned long long*)&Xs[k][tx*8];
                #pragma unroll
                for (int c=0;c<4;c++) x[c] = xp[c];
                #pragma unroll
                for (int r=0;r<RM;r++)
                    #pragma unroll
                    for (int c=0;c<4;c++)
                        asm("fma.rn.f32x2 %0, %1, %2, %0;"
                            : "+l"(acc[r][c]) : "l"(a[r]), "l"(x[c]));
            }
            __syncthreads();
        }
    }
    #pragma unroll
    for (int r=0;r<RM;r++) {
        int m = m0 + ty*RM + r;
        float bv = bias[m];
        float vals[8];
        #pragma unroll
        for (int c=0;c<4;c++) {
            unsigned long long A = acc[r][c];
            float lo = __uint_as_float((unsigned)A);
            float hi = __uint_as_float((unsigned)(A>>32));
            lo += bv; hi += bv;
            if (RELU) { lo = fmaxf(lo,0.f); hi = fmaxf(hi,0.f); }
            vals[2*c] = lo; vals[2*c+1] = hi;
        }
        float4* Cp = (float4*)(C + ((size_t)(b*M + m))*Lb + n0 + tx*8);
        Cp[0] = make_float4(vals[0],vals[1],vals[2],vals[3]);
        Cp[1] = make_float4(vals[4],vals[5],vals[6],vals[7]);
    }
}

// --------- attention GEMM (proven) with fused logits epilogue ---------
__global__ __launch_bounds__(256, 2)
void attn_gemm_kernel(const float* __restrict__ Wa1, const float* __restrict__ X,
                      const float* __restrict__ ba1, const float* __restrict__ Wa2,
                      const float* __restrict__ ba2)
{
    constexpr int MT = 64, RM = 4, K = M1;
    __shared__ float2 As[16][MT];
    __shared__ float  Xs[16][128];
    __shared__ float  red[16][128];
    const int tid = threadIdx.x;
    const int tx = tid & 15, ty = tid >> 4;
    const int colg = blockIdx.x * 128;
    const int b = colg / LL;
    const int n0 = colg % LL;
    unsigned long long acc[RM][4];
    #pragma unroll
    for (int r=0;r<RM;r++)
        #pragma unroll
        for (int c=0;c<4;c++) acc[r][c]=0ull;

    for (int kt = 0; kt < K; kt += 16) {
        #pragma unroll
        for (int i = 0; i < MT/16; i++) {
            int li = tid + i*256;
            int m = li >> 4, k = li & 15;
            float av = Wa1[m*K + kt + k];
            As[k][m] = make_float2(av, av);
        }
        #pragma unroll
        for (int i = 0; i < 8; i++) {
            int li = tid + i*256;
            int k = li >> 7, n = li & 127;
            Xs[k][n] = X[((size_t)(b*K + kt + k))*LL + n0 + n];
        }
        __syncthreads();
        #pragma unroll
        for (int k = 0; k < 16; k++) {
            unsigned long long a[RM], x[4];
            const unsigned long long* ap = (const unsigned long long*)&As[k][ty*RM];
            #pragma unroll
            for (int r=0;r<RM;r++) a[r] = ap[r];
            const unsigned long long* xp = (const unsigned long long*)&Xs[k][tx*8];
            #pragma unroll
            for (int c=0;c<4;c++) x[c] = xp[c];
            #pragma unroll
            for (int r=0;r<RM;r++)
                #pragma unroll
                for (int c=0;c<4;c++)
                    asm("fma.rn.f32x2 %0, %1, %2, %0;"
                        : "+l"(acc[r][c]) : "l"(a[r]), "l"(x[c]));
        }
        __syncthreads();
    }
    float part[8];
    #pragma unroll
    for (int k=0;k<8;k++) part[k]=0.f;
    #pragma unroll
    for (int r=0;r<RM;r++) {
        int m = ty*RM + r;
        float bv = ba1[m], w2 = Wa2[m];
        #pragma unroll
        for (int c=0;c<4;c++) {
            unsigned long long A = acc[r][c];
            float lo = fmaxf(__uint_as_float((unsigned)A) + bv, 0.f);
            float hi = fmaxf(__uint_as_float((unsigned)(A>>32)) + bv, 0.f);
            part[2*c]   += w2*lo;
            part[2*c+1] += w2*hi;
        }
    }
    #pragma unroll
    for (int k=0;k<8;k++) red[ty][tx*8+k] = part[k];
    __syncthreads();
    #pragma unroll
    for (int s=8;s>0;s>>=1) {
        if (ty < s) {
            #pragma unroll
            for (int k=0;k<8;k++) red[ty][tx*8+k] += red[ty+s][tx*8+k];
        }
        __syncthreads();
    }
    if (ty == 0) {
        float bb = ba2[0];
        #pragma unroll
        for (int k=0;k<8;k++)
            g_logits[(size_t)b*LL + n0 + tx*8 + k] = red[0][tx*8+k] + bb;
    }
}

// --------- softmax over the 32 neighbors + weighted aggregation ---------
__global__ __launch_bounds__(256)
void softagg_kernel()
{
    __shared__ float wS[NS];
    const int b = blockIdx.x / NPT, p = blockIdx.x % NPT;
    const int tid = threadIdx.x;
    if (tid < 32) {
        float lg = g_logits[b*LL + p*NS + tid];
        float m = lg;
        #pragma unroll
        for (int o=16;o>0;o>>=1) m = fmaxf(m, __shfl_xor_sync(0xffffffffu, m, o));
        float e = expf(lg - m);
        float s = e;
        #pragma unroll
        for (int o=16;o>0;o>>=1) s += __shfl_xor_sync(0xffffffffu, s, o);
        wS[tid] = e / s;
    }
    __syncthreads();
    const float4* f = (const float4*)(g_feat + ((size_t)(b*M1 + tid))*LL + p*NS);
    float a = 0.f;
    #pragma unroll
    for (int i = 0; i < 8; i++) {
        float4 v = f[i];
        a += v.x*wS[4*i] + v.y*wS[4*i+1] + v.z*wS[4*i+2] + v.w*wS[4*i+3];
    }
    g_agg[((size_t)(b*M1 + tid))*NPT + p] = a;
}

// ---------------------------------------------------------------
extern "C" void kernel_launch(void* const* d_in, const int* in_sizes, int n_in,
                              void* d_out, int out_size)
{
    const float* xyz    = (const float*)d_in[0];
    const float* points = (const float*)d_in[1];
    const int*   cent   = (const int*)  d_in[2];
    const float* gamma0 = (const float*)d_in[3];  const float* beta0 = (const float*)d_in[4];
    const float* W1     = (const float*)d_in[5];  const float* b1    = (const float*)d_in[6];
    const float* gamma1 = (const float*)d_in[7];  const float* beta1 = (const float*)d_in[8];
    const float* W2     = (const float*)d_in[9];  const float* b2    = (const float*)d_in[10];
    const float* Wres   = (const float*)d_in[11]; const float* bres  = (const float*)d_in[12];
    const float* Wa1    = (const float*)d_in[13]; const float* ba1   = (const float*)d_in[14];
    const float* Wa2    = (const float*)d_in[15]; const float* ba2   = (const float*)d_in[16];
    const float* gamma2 = (const float*)d_in[17]; const float* beta2 = (const float*)d_in[18];
    const float* Wg     = (const float*)d_in[19]; const float* bg    = (const float*)d_in[20];

    float* out = (float*)d_out;
    const int gf_elems = BB*M2*NPT;                 // 4,194,304
    float* out_gf = out + (out_size - gf_elems);    // gf goes last
    float* out_nx = (out_size > gf_elems) ? out : nullptr;

    float *px, *pinter, *pfeat, *pagg;
    float *pW1f, *pb1f, *pW2f, *pb2f, *pWgf, *pbgf;
    cudaGetSymbolAddress((void**)&px,     g_x);
    cudaGetSymbolAddress((void**)&pinter, g_inter);
    cudaGetSymbolAddress((void**)&pfeat,  g_feat);
    cudaGetSymbolAddress((void**)&pagg,   g_agg);
    cudaGetSymbolAddress((void**)&pW1f,   g_W1f);
    cudaGetSymbolAddress((void**)&pb1f,   g_b1f);
    cudaGetSymbolAddress((void**)&pW2f,   g_W2f);
    cudaGetSymbolAddress((void**)&pb2f,   g_b2f);
    cudaGetSymbolAddress((void**)&pWgf,   g_Wgf);
    cudaGetSymbolAddress((void**)&pbgf,   g_bgf);

    // 1. KNN + centroid coord output
    knn_kernel<<<BB*NPT, 256>>>(xyz, cent, out_nx);
    // 2. transpose points to point-major, then gather + standardize
    pts_transpose_kernel<<<(BB*DPTS*NN+255)/256, 256>>>(points);
    group_std_kernel<<<BB*NPT, 256>>>(xyz, cent);
    // 3. BN0 stats + fold into W1 (fused)
    chan_stats_part_kernel<<<dim3(CIN, 32), 256>>>(px, CIN, LL, 32);
    bn_fold_kernel<<<dim3(32, 3), 256>>>(W1, gamma0, beta0, b1, nullptr,
                                         M0, CIN, LL, 32, pW1f, pb1f);
    // 4. inter = relu(W1' x + b1')          [f32x2]
    gemm_kernel<128,true><<<dim3(BB*LL/128, 1), 256>>>(pW1f, px, CIN, nullptr, nullptr, 0,
                                                       pb1f, pinter, M0, LL);
    // 5. BN1 stats + fold into W2 (bias includes bres)
    chan_stats_part_kernel<<<dim3(M0, 16), 256>>>(pinter, M0, LL, 16);
    bn_fold_kernel<<<dim3(128, 3), 256>>>(W2, gamma1, beta1, b2, bres,
                                          M1, M0, LL, 16, pW2f, pb2f);
    // 6. feat = relu(W2' inter + Wres x + b')   [f32x2 dual-K]
    gemm_kernel<128,true><<<dim3(BB*LL/128, 2), 256>>>(pW2f, pinter, M0, Wres, px, CIN,
                                                       pb2f, pfeat, M1, LL);
    // 7. attention: h in-register, logits fused into GEMM epilogue
    attn_gemm_kernel<<<BB*LL/128, 256>>>(Wa1, pfeat, ba1, Wa2, ba2);
    softagg_kernel<<<BB*NPT, 256>>>();
    // 8. BN2 stats + fold into Wg
    chan_stats_part_kernel<<<dim3(M1, 4), 256>>>(pagg, M1, NPT, 4);
    bn_fold_kernel<<<dim3(512, 3), 256>>>(Wg, gamma2, beta2, bg, nullptr,
                                          M2, M1, NPT, 4, pWgf, pbgf);
    // 9. gf = relu(Wg' agg + bg')           [f32x2]
    gemm_kernel<128,true><<<dim3(BB*NPT/128, 4), 256>>>(pWgf, pagg, M1, nullptr, nullptr, 0,
                                                        pbgf, out_gf, M2, NPT);
}